// round 1
// baseline (speedup 1.0000x reference)
#include <cuda_runtime.h>

#define NUM_USERS 100000
#define NUM_ITEMS 50000
#define N_NODES   150000
#define DIM       64
#define BATCH_N   16384

// Scratch state (static __device__ globals — allocation-free rule)
__device__ float g_acc [(size_t)N_NODES * DIM];
__device__ float g_bufA[(size_t)N_NODES * DIM];
__device__ float g_bufB[(size_t)N_NODES * DIM];

static const int TOTAL4 = N_NODES * DIM / 4;   // float4 elements per buffer
static const int USER4  = NUM_USERS * DIM / 4;

// acc = ego, bufA = ego, bufB = 0
__global__ void k_init(const float* __restrict__ ue, const float* __restrict__ ie) {
    int i = blockIdx.x * blockDim.x + threadIdx.x;
    if (i >= N_NODES * DIM / 4) return;
    const int u4 = NUM_USERS * DIM / 4;
    float4 v = (i < u4) ? ((const float4*)ue)[i] : ((const float4*)ie)[i - u4];
    ((float4*)g_acc)[i]  = v;
    ((float4*)g_bufA)[i] = v;
    ((float4*)g_bufB)[i] = make_float4(0.f, 0.f, 0.f, 0.f);
}

// COO scatter SpMM: y[r] += v * x[c].  16 threads per nnz, float4 per thread.
// dir==0: x=bufA, y=bufB ; dir==1: x=bufB, y=bufA
__global__ void k_spmm(const int* __restrict__ rows, const int* __restrict__ cols,
                       const float* __restrict__ vals, int nnz, int dir) {
    int t = blockIdx.x * blockDim.x + threadIdx.x;
    int e = t >> 4;
    if (e >= nnz) return;
    int q = t & 15;
    const float* __restrict__ x = dir ? g_bufB : g_bufA;
    float* __restrict__       y = dir ? g_bufA : g_bufB;

    int   r = __ldg(rows + e);
    int   c = __ldg(cols + e);
    float v = __ldg(vals + e);

    float4 xv = ((const float4*)(x + (size_t)c * DIM))[q];
    float4 o  = make_float4(xv.x * v, xv.y * v, xv.z * v, xv.w * v);
    float* dst = y + (size_t)r * DIM + q * 4;
    asm volatile("red.global.add.v4.f32 [%0], {%1,%2,%3,%4};"
                 :: "l"(dst), "f"(o.x), "f"(o.y), "f"(o.z), "f"(o.w)
                 : "memory");
}

// acc += src ; zerobuf = 0   (src/zerobuf selected by dir)
// dir==0: src=bufB, zero=bufA ; dir==1: src=bufA, zero=bufB
__global__ void k_fix(int dir) {
    int i = blockIdx.x * blockDim.x + threadIdx.x;
    if (i >= N_NODES * DIM / 4) return;
    const float4* src  = dir ? (const float4*)g_bufA : (const float4*)g_bufB;
    float4*       zero = dir ? (float4*)g_bufB       : (float4*)g_bufA;
    float4 a = ((float4*)g_acc)[i];
    float4 s = src[i];
    a.x += s.x; a.y += s.y; a.z += s.z; a.w += s.w;
    ((float4*)g_acc)[i] = a;
    zero[i] = make_float4(0.f, 0.f, 0.f, 0.f);
}

// one warp per (user, item) pair; scale = 1/(4*4) from mean of 4 layer terms
__global__ void k_dot(const int* __restrict__ users, const int* __restrict__ items,
                      float* __restrict__ out, int batch) {
    int w    = (blockIdx.x * blockDim.x + threadIdx.x) >> 5;
    int lane = threadIdx.x & 31;
    if (w >= batch) return;
    int u  = __ldg(users + w);
    int it = __ldg(items + w);
    const float2* up = (const float2*)(g_acc + (size_t)u * DIM);
    const float2* ip = (const float2*)(g_acc + (size_t)(NUM_USERS + it) * DIM);
    float2 a = up[lane];
    float2 b = ip[lane];
    float d = a.x * b.x + a.y * b.y;
    #pragma unroll
    for (int o = 16; o; o >>= 1) d += __shfl_xor_sync(0xffffffffu, d, o);
    if (lane == 0) out[w] = d * (1.0f / 16.0f);
}

extern "C" void kernel_launch(void* const* d_in, const int* in_sizes, int n_in,
                              void* d_out, int out_size) {
    const int*   users    = (const int*)  d_in[0];
    const int*   items    = (const int*)  d_in[1];
    const int*   adj_rows = (const int*)  d_in[2];
    const int*   adj_cols = (const int*)  d_in[3];
    const float* adj_vals = (const float*)d_in[4];
    const float* user_emb = (const float*)d_in[5];
    const float* item_emb = (const float*)d_in[6];
    float* out = (float*)d_out;

    const int nnz   = in_sizes[2];
    const int batch = in_sizes[0];

    const int T = 256;
    const int total4  = N_NODES * DIM / 4;
    const int gb_elem = (total4 + T - 1) / T;
    const int gb_spmm = ((nnz * 16) + T - 1) / T;
    const int gb_dot  = ((batch * 32) + T - 1) / T;

    k_init<<<gb_elem, T>>>(user_emb, item_emb);

    // layer 1: bufA -> bufB ; acc += bufB ; bufA = 0
    k_spmm<<<gb_spmm, T>>>(adj_rows, adj_cols, adj_vals, nnz, 0);
    k_fix<<<gb_elem, T>>>(0);
    // layer 2: bufB -> bufA ; acc += bufA ; bufB = 0
    k_spmm<<<gb_spmm, T>>>(adj_rows, adj_cols, adj_vals, nnz, 1);
    k_fix<<<gb_elem, T>>>(1);
    // layer 3: bufA -> bufB ; acc += bufB ; (bufA zeroed harmlessly)
    k_spmm<<<gb_spmm, T>>>(adj_rows, adj_cols, adj_vals, nnz, 0);
    k_fix<<<gb_elem, T>>>(0);

    k_dot<<<gb_dot, T>>>(users, items, out, batch);
}

// round 2
// speedup vs baseline: 2.0481x; 2.0481x over previous
#include <cuda_runtime.h>

#define NUM_USERS 100000
#define NUM_ITEMS 50000
#define N_NODES   150000
#define DIM       64
#define NNZ_MAX   4800000

// ---- static device scratch (allocation-free rule) ----
__device__ float g_acc [(size_t)N_NODES * DIM];
__device__ float g_bufA[(size_t)N_NODES * DIM];
__device__ float g_bufB[(size_t)N_NODES * DIM];
__device__ int   g_cnt   [N_NODES];
__device__ int   g_start [N_NODES];
__device__ int   g_cursor[N_NODES];
__device__ int2  g_edges [NNZ_MAX];     // packed {col, val bits}, grouped by row
__device__ int   g_partials[256];

// acc = ego, bufA = ego, counts = 0
__global__ void k_init(const float* __restrict__ ue, const float* __restrict__ ie) {
    int i = blockIdx.x * blockDim.x + threadIdx.x;
    if (i < N_NODES / 4 * 16 / 16) { /* no-op shape hint */ }
    if (i < N_NODES * DIM / 4) {
        const int u4 = NUM_USERS * DIM / 4;
        float4 v = (i < u4) ? ((const float4*)ue)[i] : ((const float4*)ie)[i - u4];
        ((float4*)g_acc)[i]  = v;
        ((float4*)g_bufA)[i] = v;
    }
    if (i < N_NODES / 4) ((int4*)g_cnt)[i] = make_int4(0, 0, 0, 0);
}

__global__ void k_hist(const int* __restrict__ rows, int nnz) {
    int e = blockIdx.x * blockDim.x + threadIdx.x;
    if (e < nnz) atomicAdd(&g_cnt[__ldg(rows + e)], 1);
}

// inclusive scan within 1024-blocks; block totals to partials
__global__ void k_scan1(int n) {
    __shared__ int sh[1024];
    int i = blockIdx.x * 1024 + threadIdx.x;
    sh[threadIdx.x] = (i < n) ? g_cnt[i] : 0;
    __syncthreads();
    #pragma unroll
    for (int off = 1; off < 1024; off <<= 1) {
        int t = (threadIdx.x >= off) ? sh[threadIdx.x - off] : 0;
        __syncthreads();
        sh[threadIdx.x] += t;
        __syncthreads();
    }
    if (i < n) g_start[i] = sh[threadIdx.x];           // inclusive-in-block
    if (threadIdx.x == 1023) g_partials[blockIdx.x] = sh[1023];
}

__global__ void k_scan2(int nb) {
    if (threadIdx.x == 0 && blockIdx.x == 0) {
        int run = 0;
        for (int i = 0; i < nb; i++) { int t = g_partials[i]; g_partials[i] = run; run += t; }
    }
}

// exclusive global start = inclusive_in_block - cnt + block_offset
__global__ void k_scan3(int n) {
    int i = blockIdx.x * 1024 + threadIdx.x;
    if (i >= n) return;
    int s = g_start[i] - g_cnt[i] + g_partials[blockIdx.x];
    g_start[i]  = s;
    g_cursor[i] = s;
}

__global__ void k_scatter(const int* __restrict__ rows, const int* __restrict__ cols,
                          const float* __restrict__ vals, int nnz) {
    int e = blockIdx.x * blockDim.x + threadIdx.x;
    if (e >= nnz) return;
    int r   = __ldg(rows + e);
    int pos = atomicAdd(&g_cursor[r], 1);
    g_edges[pos] = make_int2(__ldg(cols + e), __float_as_int(__ldg(vals + e)));
}

// gather SpMM, one warp per row, float2 per lane; fused acc += y
// dir==0: x=bufA -> y=bufB ; dir==1: x=bufB -> y=bufA
__global__ void k_spmm_gather(int dir) {
    int w = (blockIdx.x * blockDim.x + threadIdx.x) >> 5;
    if (w >= N_NODES) return;
    int lane = threadIdx.x & 31;
    const float2* __restrict__ x = dir ? (const float2*)g_bufB : (const float2*)g_bufA;
    float2*       __restrict__ y = dir ? (float2*)g_bufA       : (float2*)g_bufB;

    int base = __ldg(&g_start[w]);
    int len  = __ldg(&g_cnt[w]);
    const int2* __restrict__ ep = g_edges + base;

    float2 s = make_float2(0.f, 0.f);
    int j = 0;
    for (; j + 4 <= len; j += 4) {
        int2 e0 = __ldg(ep + j);
        int2 e1 = __ldg(ep + j + 1);
        int2 e2 = __ldg(ep + j + 2);
        int2 e3 = __ldg(ep + j + 3);
        float2 x0 = __ldg(&x[(size_t)e0.x * 32 + lane]);
        float2 x1 = __ldg(&x[(size_t)e1.x * 32 + lane]);
        float2 x2 = __ldg(&x[(size_t)e2.x * 32 + lane]);
        float2 x3 = __ldg(&x[(size_t)e3.x * 32 + lane]);
        float v0 = __int_as_float(e0.y), v1 = __int_as_float(e1.y);
        float v2 = __int_as_float(e2.y), v3 = __int_as_float(e3.y);
        s.x = fmaf(v0, x0.x, s.x); s.y = fmaf(v0, x0.y, s.y);
        s.x = fmaf(v1, x1.x, s.x); s.y = fmaf(v1, x1.y, s.y);
        s.x = fmaf(v2, x2.x, s.x); s.y = fmaf(v2, x2.y, s.y);
        s.x = fmaf(v3, x3.x, s.x); s.y = fmaf(v3, x3.y, s.y);
    }
    for (; j < len; j++) {
        int2 e = __ldg(ep + j);
        float2 xv = __ldg(&x[(size_t)e.x * 32 + lane]);
        float v = __int_as_float(e.y);
        s.x = fmaf(v, xv.x, s.x); s.y = fmaf(v, xv.y, s.y);
    }
    size_t o = (size_t)w * 32 + lane;
    y[o] = s;
    float2 a = ((float2*)g_acc)[o];
    a.x += s.x; a.y += s.y;
    ((float2*)g_acc)[o] = a;
}

// one warp per (user, item) pair; scale 1/16 = (1/4 mean)^2
__global__ void k_dot(const int* __restrict__ users, const int* __restrict__ items,
                      float* __restrict__ out, int batch) {
    int w    = (blockIdx.x * blockDim.x + threadIdx.x) >> 5;
    int lane = threadIdx.x & 31;
    if (w >= batch) return;
    int u  = __ldg(users + w);
    int it = __ldg(items + w);
    float2 a = ((const float2*)(g_acc + (size_t)u * DIM))[lane];
    float2 b = ((const float2*)(g_acc + (size_t)(NUM_USERS + it) * DIM))[lane];
    float d = a.x * b.x + a.y * b.y;
    #pragma unroll
    for (int o = 16; o; o >>= 1) d += __shfl_xor_sync(0xffffffffu, d, o);
    if (lane == 0) out[w] = d * (1.0f / 16.0f);
}

extern "C" void kernel_launch(void* const* d_in, const int* in_sizes, int n_in,
                              void* d_out, int out_size) {
    const int*   users    = (const int*)  d_in[0];
    const int*   items    = (const int*)  d_in[1];
    const int*   adj_rows = (const int*)  d_in[2];
    const int*   adj_cols = (const int*)  d_in[3];
    const float* adj_vals = (const float*)d_in[4];
    const float* user_emb = (const float*)d_in[5];
    const float* item_emb = (const float*)d_in[6];
    float* out = (float*)d_out;

    const int nnz   = in_sizes[2];
    const int batch = in_sizes[0];

    const int T = 256;
    const int gb_elem  = (N_NODES * DIM / 4 + T - 1) / T;
    const int gb_edge  = (nnz + T - 1) / T;
    const int nb_scan  = (N_NODES + 1023) / 1024;
    const int gb_row   = (N_NODES * 32 + T - 1) / T;
    const int gb_dot   = (batch * 32 + T - 1) / T;

    // init + CSR build
    k_init<<<gb_elem, T>>>(user_emb, item_emb);
    k_hist<<<gb_edge, T>>>(adj_rows, nnz);
    k_scan1<<<nb_scan, 1024>>>(N_NODES);
    k_scan2<<<1, 32>>>(nb_scan);
    k_scan3<<<nb_scan, 1024>>>(N_NODES);
    k_scatter<<<gb_edge, T>>>(adj_rows, adj_cols, adj_vals, nnz);

    // 3 propagation layers (acc += fused into gather)
    k_spmm_gather<<<gb_row, T>>>(0);
    k_spmm_gather<<<gb_row, T>>>(1);
    k_spmm_gather<<<gb_row, T>>>(0);

    k_dot<<<gb_dot, T>>>(users, items, out, batch);
}

// round 4
// speedup vs baseline: 2.1074x; 1.0289x over previous
#include <cuda_runtime.h>
#include <cuda_fp16.h>

#define NUM_USERS 100000
#define NUM_ITEMS 50000
#define N_NODES   150000
#define DIM       64
#define NNZ_MAX   4800000

// ---- static device scratch (referenced ONLY from device code) ----
__device__ float   g_acc  [(size_t)N_NODES * DIM];            // fp32 accumulator
__device__ __half2 g_ego_h[(size_t)N_NODES * DIM / 2];        // fp16 ego copy
__device__ __half2 g_c1_h [(size_t)N_NODES * DIM / 2];        // layer-1 output
__device__ __half2 g_c2_h [(size_t)N_NODES * DIM / 2];        // layer-2 output
__device__ int   g_cnt   [N_NODES];
__device__ int   g_start [N_NODES];
__device__ int   g_cursor[N_NODES];
__device__ int2  g_edges [NNZ_MAX];
__device__ int   g_partials[256];

// fp16 ego copy + zero counters
__global__ void k_init(const float* __restrict__ ue, const float* __restrict__ ie) {
    int i = blockIdx.x * blockDim.x + threadIdx.x;   // one float4 -> two half2
    if (i < N_NODES * DIM / 4) {
        const int u4 = NUM_USERS * DIM / 4;
        float4 v = (i < u4) ? ((const float4*)ue)[i] : ((const float4*)ie)[i - u4];
        g_ego_h[i * 2]     = __float22half2_rn(make_float2(v.x, v.y));
        g_ego_h[i * 2 + 1] = __float22half2_rn(make_float2(v.z, v.w));
    }
    if (i < N_NODES / 4) ((int4*)g_cnt)[i] = make_int4(0, 0, 0, 0);
}

__global__ void k_hist(const int* __restrict__ rows, int nnz) {
    int e = blockIdx.x * blockDim.x + threadIdx.x;
    if (e < nnz) atomicAdd(&g_cnt[__ldg(rows + e)], 1);
}

// inclusive scan within 1024-blocks; block totals to partials
__global__ void k_scan1(int n) {
    __shared__ int sh[1024];
    int i = blockIdx.x * 1024 + threadIdx.x;
    sh[threadIdx.x] = (i < n) ? g_cnt[i] : 0;
    __syncthreads();
    #pragma unroll
    for (int off = 1; off < 1024; off <<= 1) {
        int t = (threadIdx.x >= off) ? sh[threadIdx.x - off] : 0;
        __syncthreads();
        sh[threadIdx.x] += t;
        __syncthreads();
    }
    if (i < n) g_start[i] = sh[threadIdx.x];
    if (threadIdx.x == 1023) g_partials[blockIdx.x] = sh[1023];
}

// parallel exclusive scan of block partials (nb <= 256)
__global__ void k_scan2(int nb) {
    __shared__ int sh[256];
    int t = threadIdx.x;
    int v = (t < nb) ? g_partials[t] : 0;
    sh[t] = v;
    __syncthreads();
    #pragma unroll
    for (int off = 1; off < 256; off <<= 1) {
        int u = (t >= off) ? sh[t - off] : 0;
        __syncthreads();
        sh[t] += u;
        __syncthreads();
    }
    if (t < nb) g_partials[t] = sh[t] - v;
}

__global__ void k_scan3(int n) {
    int i = blockIdx.x * 1024 + threadIdx.x;
    if (i >= n) return;
    int s = g_start[i] - g_cnt[i] + g_partials[blockIdx.x];
    g_start[i]  = s;
    g_cursor[i] = s;
}

__global__ void k_scatter(const int* __restrict__ rows, const int* __restrict__ cols,
                          const float* __restrict__ vals, int nnz) {
    int e = blockIdx.x * blockDim.x + threadIdx.x;
    if (e >= nnz) return;
    int r   = __ldg(rows + e);
    int pos = atomicAdd(&g_cursor[r], 1);
    g_edges[pos] = make_int2(__ldg(cols + e), __float_as_int(__ldg(vals + e)));
}

// gather SpMM, one warp per row, fp16 operands, fp32 accumulate.
// Buffers chosen from `mode` INSIDE the kernel (device globals are not
// valid pointers in host code).
// mode 0: x=ego_h, y=c1_h, acc = ego(fp32 inputs) + s
// mode 1: x=c1_h,  y=c2_h, acc += s
// mode 2: x=c2_h,  y=none, acc += s
__global__ void k_gather(int mode, const float* __restrict__ ue,
                         const float* __restrict__ ie) {
    int w = (blockIdx.x * blockDim.x + threadIdx.x) >> 5;
    if (w >= N_NODES) return;
    int lane = threadIdx.x & 31;

    const __half2* __restrict__ x =
        (mode == 0) ? g_ego_h : (mode == 1) ? g_c1_h : g_c2_h;

    int base = __ldg(&g_start[w]);
    int len  = __ldg(&g_cnt[w]);
    const int2* __restrict__ ep = g_edges + base;

    float2 s = make_float2(0.f, 0.f);
    int j = 0;
    for (; j + 4 <= len; j += 4) {
        int2 e0 = __ldg(ep + j);
        int2 e1 = __ldg(ep + j + 1);
        int2 e2 = __ldg(ep + j + 2);
        int2 e3 = __ldg(ep + j + 3);
        float2 x0 = __half22float2(__ldg(&x[(size_t)e0.x * 32 + lane]));
        float2 x1 = __half22float2(__ldg(&x[(size_t)e1.x * 32 + lane]));
        float2 x2 = __half22float2(__ldg(&x[(size_t)e2.x * 32 + lane]));
        float2 x3 = __half22float2(__ldg(&x[(size_t)e3.x * 32 + lane]));
        float v0 = __int_as_float(e0.y), v1 = __int_as_float(e1.y);
        float v2 = __int_as_float(e2.y), v3 = __int_as_float(e3.y);
        s.x = fmaf(v0, x0.x, s.x); s.y = fmaf(v0, x0.y, s.y);
        s.x = fmaf(v1, x1.x, s.x); s.y = fmaf(v1, x1.y, s.y);
        s.x = fmaf(v2, x2.x, s.x); s.y = fmaf(v2, x2.y, s.y);
        s.x = fmaf(v3, x3.x, s.x); s.y = fmaf(v3, x3.y, s.y);
    }
    for (; j < len; j++) {
        int2 e = __ldg(ep + j);
        float2 xv = __half22float2(__ldg(&x[(size_t)e.x * 32 + lane]));
        float v = __int_as_float(e.y);
        s.x = fmaf(v, xv.x, s.x); s.y = fmaf(v, xv.y, s.y);
    }

    size_t o = (size_t)w * 32 + lane;
    if (mode == 0)      g_c1_h[o] = __float22half2_rn(s);
    else if (mode == 1) g_c2_h[o] = __float22half2_rn(s);

    float2 a;
    if (mode == 0) {
        const float2* __restrict__ src = (w < NUM_USERS)
            ? (const float2*)ue + (size_t)w * 32
            : (const float2*)ie + (size_t)(w - NUM_USERS) * 32;
        a = __ldg(src + lane);
    } else {
        a = ((float2*)g_acc)[o];
    }
    a.x += s.x; a.y += s.y;
    ((float2*)g_acc)[o] = a;
}

// one warp per (user, item) pair; scale 1/16 = (1/4)^2 from the two means
__global__ void k_dot(const int* __restrict__ users, const int* __restrict__ items,
                      float* __restrict__ out, int batch) {
    int w    = (blockIdx.x * blockDim.x + threadIdx.x) >> 5;
    int lane = threadIdx.x & 31;
    if (w >= batch) return;
    int u  = __ldg(users + w);
    int it = __ldg(items + w);
    float2 a = ((const float2*)(g_acc + (size_t)u * DIM))[lane];
    float2 b = ((const float2*)(g_acc + (size_t)(NUM_USERS + it) * DIM))[lane];
    float d = a.x * b.x + a.y * b.y;
    #pragma unroll
    for (int o = 16; o; o >>= 1) d += __shfl_xor_sync(0xffffffffu, d, o);
    if (lane == 0) out[w] = d * (1.0f / 16.0f);
}

extern "C" void kernel_launch(void* const* d_in, const int* in_sizes, int n_in,
                              void* d_out, int out_size) {
    const int*   users    = (const int*)  d_in[0];
    const int*   items    = (const int*)  d_in[1];
    const int*   adj_rows = (const int*)  d_in[2];
    const int*   adj_cols = (const int*)  d_in[3];
    const float* adj_vals = (const float*)d_in[4];
    const float* user_emb = (const float*)d_in[5];
    const float* item_emb = (const float*)d_in[6];
    float* out = (float*)d_out;

    const int nnz   = in_sizes[2];
    const int batch = in_sizes[0];

    const int T = 256;
    const int gb_elem = (N_NODES * DIM / 4 + T - 1) / T;
    const int gb_edge = (nnz + T - 1) / T;
    const int nb_scan = (N_NODES + 1023) / 1024;
    const int gb_row  = (N_NODES * 32 + T - 1) / T;
    const int gb_dot  = (batch * 32 + T - 1) / T;

    k_init<<<gb_elem, T>>>(user_emb, item_emb);
    k_hist<<<gb_edge, T>>>(adj_rows, nnz);
    k_scan1<<<nb_scan, 1024>>>(N_NODES);
    k_scan2<<<1, 256>>>(nb_scan);
    k_scan3<<<nb_scan, 1024>>>(N_NODES);
    k_scatter<<<gb_edge, T>>>(adj_rows, adj_cols, adj_vals, nnz);

    k_gather<<<gb_row, T>>>(0, user_emb, item_emb);
    k_gather<<<gb_row, T>>>(1, user_emb, item_emb);
    k_gather<<<gb_row, T>>>(2, user_emb, item_emb);

    k_dot<<<gb_dot, T>>>(users, items, out, batch);
}

// round 5
// speedup vs baseline: 2.8534x; 1.3540x over previous
#include <cuda_runtime.h>
#include <cuda_fp16.h>

#define NUM_USERS 100000
#define NUM_ITEMS 50000
#define N_NODES   150000
#define DIM       64
#define NNZ_MAX   4800000
#define FULL      0xffffffffu

// ---- static device scratch (referenced ONLY from device code) ----
__device__ float   g_acc  [(size_t)N_NODES * DIM];      // fp32: ego + c1 + c2
__device__ __half2 g_ego_h[(size_t)N_NODES * DIM / 2];
__device__ __half2 g_c1_h [(size_t)N_NODES * DIM / 2];
__device__ __half2 g_c2_h [(size_t)N_NODES * DIM / 2];
__device__ int   g_cnt   [N_NODES];
__device__ int   g_start [N_NODES];
__device__ int   g_cursor[N_NODES];
__device__ int2  g_edges [NNZ_MAX];
__device__ int   g_partials[256];

// fused: fp16 ego copy + zero counters + row histogram
__global__ void k_init_hist(const float* __restrict__ ue, const float* __restrict__ ie,
                            const int* __restrict__ rows, int nnz) {
    int i = blockIdx.x * blockDim.x + threadIdx.x;
    if (i < N_NODES * DIM / 4) {
        const int u4 = NUM_USERS * DIM / 4;
        float4 v = (i < u4) ? ((const float4*)ue)[i] : ((const float4*)ie)[i - u4];
        g_ego_h[i * 2]     = __float22half2_rn(make_float2(v.x, v.y));
        g_ego_h[i * 2 + 1] = __float22half2_rn(make_float2(v.z, v.w));
    }
    if (i < N_NODES / 4) ((int4*)g_cnt)[i] = make_int4(0, 0, 0, 0);
}

__global__ void k_hist(const int* __restrict__ rows, int nnz) {
    int e = blockIdx.x * blockDim.x + threadIdx.x;
    if (e < nnz) atomicAdd(&g_cnt[__ldg(rows + e)], 1);
}

__global__ void k_scan1(int n) {
    __shared__ int sh[1024];
    int i = blockIdx.x * 1024 + threadIdx.x;
    sh[threadIdx.x] = (i < n) ? g_cnt[i] : 0;
    __syncthreads();
    #pragma unroll
    for (int off = 1; off < 1024; off <<= 1) {
        int t = (threadIdx.x >= off) ? sh[threadIdx.x - off] : 0;
        __syncthreads();
        sh[threadIdx.x] += t;
        __syncthreads();
    }
    if (i < n) g_start[i] = sh[threadIdx.x];
    if (threadIdx.x == 1023) g_partials[blockIdx.x] = sh[1023];
}

__global__ void k_scan2(int nb) {
    __shared__ int sh[256];
    int t = threadIdx.x;
    int v = (t < nb) ? g_partials[t] : 0;
    sh[t] = v;
    __syncthreads();
    #pragma unroll
    for (int off = 1; off < 256; off <<= 1) {
        int u = (t >= off) ? sh[t - off] : 0;
        __syncthreads();
        sh[t] += u;
        __syncthreads();
    }
    if (t < nb) g_partials[t] = sh[t] - v;
}

__global__ void k_scan3(int n) {
    int i = blockIdx.x * 1024 + threadIdx.x;
    if (i >= n) return;
    int s = g_start[i] - g_cnt[i] + g_partials[blockIdx.x];
    g_start[i]  = s;
    g_cursor[i] = s;
}

__global__ void k_scatter(const int* __restrict__ rows, const int* __restrict__ cols,
                          const float* __restrict__ vals, int nnz) {
    int e = blockIdx.x * blockDim.x + threadIdx.x;
    if (e >= nnz) return;
    int r   = __ldg(rows + e);
    int pos = atomicAdd(&g_cursor[r], 1);
    g_edges[pos] = make_int2(__ldg(cols + e), __float_as_int(__ldg(vals + e)));
}

// warp-cooperative row gather: lane-parallel edge loads + shfl broadcast.
// One LDG.64 per 32 edges for metadata, one LDG.32 (128B/warp) per edge for x.
__device__ __forceinline__ float2 row_gather(const __half2* __restrict__ x,
                                             int base, int len, int lane) {
    const int2* __restrict__ ep = g_edges + base;
    float2 s = make_float2(0.f, 0.f);
    int nfull = len & ~31;
    for (int chunk = 0; chunk < nfull; chunk += 32) {
        int2 e = __ldg(ep + chunk + lane);
        #pragma unroll 4
        for (int k = 0; k < 32; k++) {
            int   col = __shfl_sync(FULL, e.x, k);
            float v   = __int_as_float(__shfl_sync(FULL, e.y, k));
            float2 xv = __half22float2(__ldg(&x[(size_t)col * 32 + lane]));
            s.x = fmaf(v, xv.x, s.x);
            s.y = fmaf(v, xv.y, s.y);
        }
    }
    int rem = len - nfull;
    if (rem) {
        int2 e = make_int2(0, 0);
        if (lane < rem) e = __ldg(ep + nfull + lane);
        for (int k = 0; k < rem; k++) {
            int   col = __shfl_sync(FULL, e.x, k);
            float v   = __int_as_float(__shfl_sync(FULL, e.y, k));
            float2 xv = __half22float2(__ldg(&x[(size_t)col * 32 + lane]));
            s.x = fmaf(v, xv.x, s.x);
            s.y = fmaf(v, xv.y, s.y);
        }
    }
    return s;
}

// mode 0: c1 = A @ ego_h ; acc = ego(fp32) + c1
// mode 1: c2 = A @ c1_h  ; acc += c2
__global__ void k_gather(int mode, const float* __restrict__ ue,
                         const float* __restrict__ ie) {
    int w = (blockIdx.x * blockDim.x + threadIdx.x) >> 5;
    if (w >= N_NODES) return;
    int lane = threadIdx.x & 31;

    const __half2* __restrict__ x = mode ? g_c1_h : g_ego_h;
    int base = __ldg(&g_start[w]);
    int len  = __ldg(&g_cnt[w]);

    float2 s = row_gather(x, base, len, lane);

    size_t o = (size_t)w * 32 + lane;
    float2 a;
    if (mode == 0) {
        g_c1_h[o] = __float22half2_rn(s);
        const float2* __restrict__ src = (w < NUM_USERS)
            ? (const float2*)ue + (size_t)w * 32
            : (const float2*)ie + (size_t)(w - NUM_USERS) * 32;
        a = __ldg(src + lane);
    } else {
        g_c2_h[o] = __float22half2_rn(s);
        a = ((float2*)g_acc)[o];
    }
    a.x += s.x; a.y += s.y;
    ((float2*)g_acc)[o] = a;
}

// lazy layer 3 + dot: one warp per (user,item) pair.
// final[row] = acc[row] + (A @ c2)[row], gathered on demand.
__global__ void k_dot(const int* __restrict__ users, const int* __restrict__ items,
                      float* __restrict__ out, int batch) {
    int w    = (blockIdx.x * blockDim.x + threadIdx.x) >> 5;
    int lane = threadIdx.x & 31;
    if (w >= batch) return;

    int r0 = __ldg(users + w);
    int r1 = NUM_USERS + __ldg(items + w);

    float2 va, vb;
    {
        float2 s = row_gather(g_c2_h, __ldg(&g_start[r0]), __ldg(&g_cnt[r0]), lane);
        float2 a = __ldg(&((const float2*)g_acc)[(size_t)r0 * 32 + lane]);
        va = make_float2(a.x + s.x, a.y + s.y);
    }
    {
        float2 s = row_gather(g_c2_h, __ldg(&g_start[r1]), __ldg(&g_cnt[r1]), lane);
        float2 a = __ldg(&((const float2*)g_acc)[(size_t)r1 * 32 + lane]);
        vb = make_float2(a.x + s.x, a.y + s.y);
    }

    float d = va.x * vb.x + va.y * vb.y;
    #pragma unroll
    for (int o = 16; o; o >>= 1) d += __shfl_xor_sync(FULL, d, o);
    if (lane == 0) out[w] = d * (1.0f / 16.0f);
}

extern "C" void kernel_launch(void* const* d_in, const int* in_sizes, int n_in,
                              void* d_out, int out_size) {
    const int*   users    = (const int*)  d_in[0];
    const int*   items    = (const int*)  d_in[1];
    const int*   adj_rows = (const int*)  d_in[2];
    const int*   adj_cols = (const int*)  d_in[3];
    const float* adj_vals = (const float*)d_in[4];
    const float* user_emb = (const float*)d_in[5];
    const float* item_emb = (const float*)d_in[6];
    float* out = (float*)d_out;

    const int nnz   = in_sizes[2];
    const int batch = in_sizes[0];

    const int T = 256;
    const int gb_elem = (N_NODES * DIM / 4 + T - 1) / T;
    const int gb_edge = (nnz + T - 1) / T;
    const int nb_scan = (N_NODES + 1023) / 1024;
    const int gb_row  = (N_NODES * 32 + T - 1) / T;
    const int gb_dot  = (batch * 32 + T - 1) / T;

    k_init_hist<<<gb_elem, T>>>(user_emb, item_emb, adj_rows, nnz);
    k_hist<<<gb_edge, T>>>(adj_rows, nnz);
    k_scan1<<<nb_scan, 1024>>>(N_NODES);
    k_scan2<<<1, 256>>>(nb_scan);
    k_scan3<<<nb_scan, 1024>>>(N_NODES);
    k_scatter<<<gb_edge, T>>>(adj_rows, adj_cols, adj_vals, nnz);

    k_gather<<<gb_row, T>>>(0, user_emb, item_emb);
    k_gather<<<gb_row, T>>>(1, user_emb, item_emb);

    k_dot<<<gb_dot, T>>>(users, items, out, batch);
}